// round 10
// baseline (speedup 1.0000x reference)
#include <cuda_runtime.h>
#include <cuda_bf16.h>
#include <cstdint>

// DeepFeatureLoss via mma.sync.m16n8k16 bf16 HMMA.
//   D_feat = cq_i(init) + 2L*f1_i.f2_j(MMA,3-term split,6 ks) + cf_j(epilogue)
//   D_sp   = full spatial log2 score via MMA (3-split coords, 6 cross terms +
//            row/col consts in K-slots, 2 ks)  [R8-validated form]
//   eq = ex2(D_feat), ep = ex2(D_sp)
//   sum_j (p-q)^2 = Bb/Zp^2 - 2A/(Zp Zq) + C/Zq^2
// Feature MMA chain split 3+3 for latency; B fragments read as paired LDS.64
// from a rotated conflict-free smem layout.

#define SIGMA_INV 20.0f
#define LOG2E     1.4426950408889634f
#define KSH       44.0f
#define MAX_ROWS  16384
#define JCH       16
#define MT        128
#define NT        128

typedef unsigned long long ull;
typedef unsigned int  u32;
typedef unsigned short u16;

static __device__ __align__(16) u16 g_Af[(size_t)MAX_ROWS * 128];  // 64 u32 words/row, 48 used
static __device__ __align__(16) u16 g_Bf[(size_t)MAX_ROWS * 128];
static __device__ __align__(16) u16 g_As[(size_t)MAX_ROWS * 64];   // 32 u32 words/row, 12 used
static __device__ __align__(16) u16 g_Bs[(size_t)MAX_ROWS * 64];
static __device__ float g_cf[MAX_ROWS];                             // -L|f2|^2
static __device__ float g_rc[MAX_ROWS];                             // KSH - L|f1|^2
static __device__ __align__(16) float4 g_part[(size_t)MAX_ROWS * JCH * 2];

// ---------- helpers ----------
__device__ __forceinline__ ull f2add(ull a, ull b) {
    ull d; asm("add.rn.f32x2 %0, %1, %2;" : "=l"(d) : "l"(a), "l"(b)); return d;
}
__device__ __forceinline__ ull f2fma(ull a, ull b, ull c) {
    ull d; asm("fma.rn.f32x2 %0, %1, %2, %3;" : "=l"(d) : "l"(a), "l"(b), "l"(c)); return d;
}
__device__ __forceinline__ float ex2f(float x) {
    float y; asm("ex2.approx.f32 %0, %1;" : "=f"(y) : "f"(x)); return y;
}
__device__ __forceinline__ void unpack2(ull v, float& lo, float& hi) {
    asm("mov.b64 {%0, %1}, %2;" : "=f"(lo), "=f"(hi) : "l"(v));
}
__device__ __forceinline__ void unpack2u(ull v, u32& lo, u32& hi) {
    asm("mov.b64 {%0, %1}, %2;" : "=r"(lo), "=r"(hi) : "l"(v));
}
__device__ __forceinline__ ull pack2(float lo, float hi) {
    ull v; asm("mov.b64 %0, {%1, %2};" : "=l"(v) : "f"(lo), "f"(hi)); return v;
}
__device__ __forceinline__ u16 f2bf(float x) {
    __nv_bfloat16 b = __float2bfloat16(x);
    return *reinterpret_cast<u16*>(&b);
}
__device__ __forceinline__ float bf2f(u16 u) {
    __nv_bfloat16 b = *reinterpret_cast<__nv_bfloat16*>(&u);
    return __bfloat162float(b);
}
__device__ __forceinline__ u32 pk(u16 lo, u16 hi) { return (u32)lo | ((u32)hi << 16); }

__device__ __forceinline__ void mma16816(float& d0, float& d1, float& d2, float& d3,
                                         const u32* a, u32 b0, u32 b1)
{
    asm("mma.sync.aligned.m16n8k16.row.col.f32.bf16.bf16.f32 "
        "{%0,%1,%2,%3},{%4,%5,%6,%7},{%8,%9},{%0,%1,%2,%3};"
        : "+f"(d0), "+f"(d1), "+f"(d2), "+f"(d3)
        : "r"(a[0]), "r"(a[1]), "r"(a[2]), "r"(a[3]), "r"(b0), "r"(b1));
}

// ---------- prep: 2 threads per row ----------
__global__ void prep_kernel(const float* __restrict__ points,
                            const float* __restrict__ fea1,
                            const float* __restrict__ fea2,
                            int BN)
{
    int idx = blockIdx.x * 128 + threadIdx.x;
    int g = idx >> 1, side = idx & 1;
    if (g >= BN) return;
    const u16 one = f2bf(1.0f);

    if (side == 0) {
        // feature A: 3-term split layout [ah | al | ah]
        float a[32]; float na = 0.f;
        const float4* F1 = (const float4*)(fea1 + (size_t)g * 32);
#pragma unroll
        for (int q = 0; q < 8; q++) {
            float4 v = F1[q];
            a[4*q] = v.x; a[4*q+1] = v.y; a[4*q+2] = v.z; a[4*q+3] = v.w;
            na = fmaf(v.x,v.x, fmaf(v.y,v.y, fmaf(v.z,v.z, fmaf(v.w,v.w, na))));
        }
        u16 ah[32], al[32];
#pragma unroll
        for (int k = 0; k < 32; k++) {
            ah[k] = f2bf(a[k]); al[k] = f2bf(a[k] - bf2f(ah[k]));
        }
        u32* Af = (u32*)&g_Af[(size_t)g * 128];
#pragma unroll
        for (int k = 0; k < 16; k++) {
            u32 h = pk(ah[2*k], ah[2*k+1]);
            Af[k] = h;
            Af[16 + k] = pk(al[2*k], al[2*k+1]);
            Af[32 + k] = h;
        }
        g_rc[g] = KSH - na * LOG2E;

        // spatial A row (R8 layout: 6 cross terms x3 + consts, 24 u16)
        float u0 = points[(size_t)g*3+0] * SIGMA_INV;
        float u1 = points[(size_t)g*3+1] * SIGMA_INV;
        float u2 = points[(size_t)g*3+2] * SIGMA_INV;
        float uu[3] = {u0, u1, u2};
        float ci = -(u0*u0 + u1*u1 + u2*u2) * LOG2E;
        u16 uh[3], um[3], ul[3];
#pragma unroll
        for (int c = 0; c < 3; c++) {
            float x = uu[c];
            uh[c] = f2bf(x); float r1 = x - bf2f(uh[c]);
            um[c] = f2bf(r1); ul[c] = f2bf(r1 - bf2f(um[c]));
        }
        u16 cih = f2bf(ci); float r3 = ci - bf2f(cih);
        u16 cim = f2bf(r3); u16 cil = f2bf(r3 - bf2f(cim));

        u16 ta[24];
#pragma unroll
        for (int c = 0; c < 3; c++) {
            ta[c] = uh[c]; ta[3+c] = uh[c]; ta[6+c] = um[c];
            ta[9+c] = uh[c]; ta[12+c] = ul[c]; ta[15+c] = um[c];
            ta[21+c] = one;
        }
        ta[18] = cih; ta[19] = cim; ta[20] = cil;
        u32* As = (u32*)&g_As[(size_t)g * 64];
#pragma unroll
        for (int w = 0; w < 12; w++) As[w] = pk(ta[2*w], ta[2*w+1]);
#pragma unroll
        for (int w = 12; w < 32; w++) As[w] = 0;
    } else {
        float bb[32]; float nb = 0.f;
        const float4* F2 = (const float4*)(fea2 + (size_t)g * 32);
#pragma unroll
        for (int q = 0; q < 8; q++) {
            float4 w = F2[q];
            nb = fmaf(w.x,w.x, fmaf(w.y,w.y, fmaf(w.z,w.z, fmaf(w.w,w.w, nb))));
            float s = 2.f * LOG2E;
            bb[4*q] = s*w.x; bb[4*q+1] = s*w.y; bb[4*q+2] = s*w.z; bb[4*q+3] = s*w.w;
        }
        u16 bh[32], bl[32];
#pragma unroll
        for (int k = 0; k < 32; k++) {
            bh[k] = f2bf(bb[k]); bl[k] = f2bf(bb[k] - bf2f(bh[k]));
        }
        u32* Bf = (u32*)&g_Bf[(size_t)g * 128];
#pragma unroll
        for (int k = 0; k < 16; k++) {
            u32 h = pk(bh[2*k], bh[2*k+1]);
            Bf[k] = h;
            Bf[16 + k] = h;
            Bf[32 + k] = pk(bl[2*k], bl[2*k+1]);
        }
        g_cf[g] = -nb * LOG2E;

        // spatial B row
        float u0 = points[(size_t)g*3+0] * SIGMA_INV;
        float u1 = points[(size_t)g*3+1] * SIGMA_INV;
        float u2 = points[(size_t)g*3+2] * SIGMA_INV;
        float uu[3] = {u0, u1, u2};
        float cs = -(u0*u0 + u1*u1 + u2*u2) * LOG2E;
        u16 vh[3], vm[3], vl[3];
#pragma unroll
        for (int c = 0; c < 3; c++) {
            float y = 2.f * LOG2E * uu[c];
            vh[c] = f2bf(y); float r2 = y - bf2f(vh[c]);
            vm[c] = f2bf(r2); vl[c] = f2bf(r2 - bf2f(vm[c]));
        }
        u16 csh = f2bf(cs); float r3 = cs - bf2f(csh);
        u16 csm = f2bf(r3); u16 csl = f2bf(r3 - bf2f(csm));

        u16 tb[24];
#pragma unroll
        for (int c = 0; c < 3; c++) {
            tb[c] = vh[c]; tb[3+c] = vm[c]; tb[6+c] = vh[c];
            tb[9+c] = vl[c]; tb[12+c] = vh[c]; tb[15+c] = vm[c];
            tb[18+c] = one;
        }
        tb[21] = csh; tb[22] = csm; tb[23] = csl;
        u32* Bs = (u32*)&g_Bs[(size_t)g * 64];
#pragma unroll
        for (int w = 0; w < 12; w++) Bs[w] = pk(tb[2*w], tb[2*w+1]);
#pragma unroll
        for (int w = 12; w < 32; w++) Bs[w] = 0;
    }
}

// ---------- main ----------
__global__ __launch_bounds__(128, 4) void main_kernel(int N)
{
    // feature B: 128 rows x 32 ull (paired+rotated); spatial B: 128 x 8 ull
    __shared__ __align__(16) ull sBfU[128 * 32];
    __shared__ __align__(16) ull sBsU[128 * 8];
    __shared__ float sCf[128];

    const int tid = threadIdx.x;
    const int w = tid >> 5, l = tid & 31, g = l >> 2, t = l & 3;
    const int rowtile = blockIdx.x >> 4;
    const int chunk   = blockIdx.x & 15;
    const int rowbase = rowtile * MT;
    const int b  = rowbase / N;
    const int jc = N / JCH;                 // 256
    const int j0 = b * N + chunk * jc;
    const int ntiles = jc / NT;             // 2

    const u32* Af = (const u32*)g_Af;
    const u32* As = (const u32*)g_As;

    // A fragments
    u32 af[2][6][4], asp[2][2][4];
#pragma unroll
    for (int rt = 0; rt < 2; rt++) {
        int r0 = rowbase + 32 * w + 16 * rt + g;
#pragma unroll
        for (int ks = 0; ks < 6; ks++) {
            af[rt][ks][0] = Af[(size_t)r0 * 64 + t + 8 * ks];
            af[rt][ks][1] = Af[(size_t)(r0 + 8) * 64 + t + 8 * ks];
            af[rt][ks][2] = Af[(size_t)r0 * 64 + t + 4 + 8 * ks];
            af[rt][ks][3] = Af[(size_t)(r0 + 8) * 64 + t + 4 + 8 * ks];
        }
#pragma unroll
        for (int ks = 0; ks < 2; ks++) {
            asp[rt][ks][0] = As[(size_t)r0 * 32 + t + 8 * ks];
            asp[rt][ks][1] = As[(size_t)(r0 + 8) * 32 + t + 8 * ks];
            asp[rt][ks][2] = As[(size_t)r0 * 32 + t + 4 + 8 * ks];
            asp[rt][ks][3] = As[(size_t)(r0 + 8) * 32 + t + 4 + 8 * ks];
        }
    }
    // feature row consts (folded into MMA accumulator init)
    float cq4[4];
#pragma unroll
    for (int h = 0; h < 4; h++)
        cq4[h] = g_rc[rowbase + 32 * w + 16 * (h >> 1) + 8 * (h & 1) + g];

    ull Z[4] = {0,0,0,0}, S[4] = {0,0,0,0};
    float Aa[4] = {0.f, 0.f, 0.f, 0.f};

    for (int jt = 0; jt < ntiles; jt++) {
        __syncthreads();
        const int jrow = j0 + jt * NT;
        // ---- stage feature B: thread = row, 6 ks units ----
        {
            const uint4* src = (const uint4*)&g_Bf[(size_t)(jrow + tid) * 128];
            ull* dstrow = &sBfU[tid * 32];
            const int rot4 = 4 * (tid & 7);
#pragma unroll
            for (int u = 0; u < 6; u++) {
                uint4 lo = src[2 * u], hi = src[2 * u + 1];
                int base = (4 * u + rot4) & 31;
                *(uint4*)&dstrow[base]     = make_uint4(lo.x, hi.x, lo.y, hi.y);
                *(uint4*)&dstrow[base + 2] = make_uint4(lo.z, hi.z, lo.w, hi.w);
            }
            // ---- stage spatial B: 4 uint4 -> 8 paired ulls ----
            const uint4* ss = (const uint4*)&g_Bs[(size_t)(jrow + tid) * 64];
            uint4 q0 = ss[0], q1 = ss[1], q2 = ss[2], q3 = ss[3];
            ull* dsts = &sBsU[tid * 8];
            *(uint4*)&dsts[0] = make_uint4(q0.x, q1.x, q0.y, q1.y);
            *(uint4*)&dsts[2] = make_uint4(q0.z, q1.z, q0.w, q1.w);
            *(uint4*)&dsts[4] = make_uint4(q2.x, q3.x, q2.y, q3.y);
            *(uint4*)&dsts[6] = make_uint4(q2.z, q3.z, q2.w, q3.w);
            sCf[tid] = g_cf[jrow + tid];
        }
        __syncthreads();

#pragma unroll 1
        for (int ns = 0; ns < 16; ns++) {
            const int n = ns * 8 + g;
            const ull* rowF = &sBfU[n * 32];
            const ull* rowS = &sBsU[n * 8];
            ull F[6], Sp[2];
#pragma unroll
            for (int ks = 0; ks < 6; ks++)
                F[ks] = rowF[(4 * ks + t + 4 * g) & 31];
            Sp[0] = rowS[t];
            Sp[1] = rowS[4 + t];
            float2 cf2 = *(const float2*)&sCf[ns * 8 + 2 * t];

#pragma unroll
            for (int rt = 0; rt < 2; rt++) {
                const int h0 = 2 * rt, h1 = 2 * rt + 1;
                // feature chain A (init = cq), chain B (init = 0)
                float a0 = cq4[h0], a1 = cq4[h0], a2 = cq4[h1], a3 = cq4[h1];
                float b0 = 0.f, b1 = 0.f, b2 = 0.f, b3 = 0.f;
                float e0 = 0.f, e1 = 0.f, e2 = 0.f, e3 = 0.f;
#pragma unroll
                for (int ks = 0; ks < 3; ks++) {
                    u32 lo, hi; unpack2u(F[ks], lo, hi);
                    mma16816(a0, a1, a2, a3, af[rt][ks], lo, hi);
                }
#pragma unroll
                for (int ks = 3; ks < 6; ks++) {
                    u32 lo, hi; unpack2u(F[ks], lo, hi);
                    mma16816(b0, b1, b2, b3, af[rt][ks], lo, hi);
                }
#pragma unroll
                for (int ks = 0; ks < 2; ks++) {
                    u32 lo, hi; unpack2u(Sp[ks], lo, hi);
                    mma16816(e0, e1, e2, e3, asp[rt][ks], lo, hi);
                }
                float sq0 = (a0 + b0) + cf2.x;
                float sq1 = (a1 + b1) + cf2.y;
                float sq2 = (a2 + b2) + cf2.x;
                float sq3 = (a3 + b3) + cf2.y;

                {
                    float eq = ex2f(sq0), ep = ex2f(e0);
                    ull e = pack2(eq, ep);
                    Z[h0] = f2add(Z[h0], e); S[h0] = f2fma(e, e, S[h0]);
                    Aa[h0] = fmaf(ep, eq, Aa[h0]);
                }
                {
                    float eq = ex2f(sq1), ep = ex2f(e1);
                    ull e = pack2(eq, ep);
                    Z[h0] = f2add(Z[h0], e); S[h0] = f2fma(e, e, S[h0]);
                    Aa[h0] = fmaf(ep, eq, Aa[h0]);
                }
                {
                    float eq = ex2f(sq2), ep = ex2f(e2);
                    ull e = pack2(eq, ep);
                    Z[h1] = f2add(Z[h1], e); S[h1] = f2fma(e, e, S[h1]);
                    Aa[h1] = fmaf(ep, eq, Aa[h1]);
                }
                {
                    float eq = ex2f(sq3), ep = ex2f(e3);
                    ull e = pack2(eq, ep);
                    Z[h1] = f2add(Z[h1], e); S[h1] = f2fma(e, e, S[h1]);
                    Aa[h1] = fmaf(ep, eq, Aa[h1]);
                }
            }
        }
    }

    // quad-reduce over t, write partials
#pragma unroll
    for (int h = 0; h < 4; h++) {
        float Zq, Zp, C, Bb;
        unpack2(Z[h], Zq, Zp);
        unpack2(S[h], C, Bb);
        float A_ = Aa[h];
#pragma unroll
        for (int m = 1; m <= 2; m <<= 1) {
            Zq += __shfl_xor_sync(0xffffffffu, Zq, m);
            Zp += __shfl_xor_sync(0xffffffffu, Zp, m);
            C  += __shfl_xor_sync(0xffffffffu, C,  m);
            Bb += __shfl_xor_sync(0xffffffffu, Bb, m);
            A_ += __shfl_xor_sync(0xffffffffu, A_, m);
        }
        if (t == 0) {
            int row = rowbase + 32 * w + 16 * (h >> 1) + 8 * (h & 1) + g;
            size_t p = ((size_t)row * JCH + chunk) * 2;
            g_part[p + 0] = make_float4(Zq, A_, C, Zp);
            g_part[p + 1] = make_float4(Bb, 0.f, 0.f, 0.f);
        }
    }
}

// ---------- init / reduce ----------
__global__ void init_kernel(float* out, int B)
{
    if (threadIdx.x < B) out[threadIdx.x] = 0.f;
}

// 4 threads per row; 32 rows per block; 16 chunks
__global__ __launch_bounds__(128) void reduce_kernel(
    const float* __restrict__ weights,
    float* __restrict__ out, int N)
{
    __shared__ float sred[4];
    const int tid = threadIdx.x;
    const int r = blockIdx.x * 32 + (tid >> 2);
    const int t = tid & 3;
    const int b = (blockIdx.x * 32) / N;

    const float4* base = &g_part[(size_t)r * JCH * 2];
    float Zq = 0.f, A = 0.f, C = 0.f, Zp = 0.f, Bb = 0.f;
#pragma unroll
    for (int kk = 0; kk < 4; kk++) {
        int k = t + 4 * kk;
        float4 p0 = base[2 * k + 0];
        float4 p1 = base[2 * k + 1];
        Zq += p0.x; A += p0.y; C += p0.z; Zp += p0.w; Bb += p1.x;
    }
#pragma unroll
    for (int m = 1; m <= 2; m <<= 1) {
        Zq += __shfl_xor_sync(0xffffffffu, Zq, m);
        Zp += __shfl_xor_sync(0xffffffffu, Zp, m);
        C  += __shfl_xor_sync(0xffffffffu, C,  m);
        Bb += __shfl_xor_sync(0xffffffffu, Bb, m);
        A  += __shfl_xor_sync(0xffffffffu, A,  m);
    }
    float v = 0.f;
    if (t == 0) {
        float izp = 1.f / Zp, izq = 1.f / Zq;
        float loss = Bb * izp * izp - 2.f * A * izp * izq + C * izq * izq;
        v = weights[r] * loss;
    }
#pragma unroll
    for (int off = 16; off > 0; off >>= 1)
        v += __shfl_down_sync(0xffffffffu, v, off);
    if ((tid & 31) == 0) sred[tid >> 5] = v;
    __syncthreads();
    if (tid == 0) {
        atomicAdd(&out[b], sred[0] + sred[1] + sred[2] + sred[3]);
    }
}

extern "C" void kernel_launch(void* const* d_in, const int* in_sizes, int n_in,
                              void* d_out, int out_size)
{
    const float* points  = (const float*)d_in[0];  // [B,N,3]
    const float* fea1    = (const float*)d_in[1];  // [B,N,32]
    const float* fea2    = (const float*)d_in[2];  // [B,N,32]
    const float* weights = (const float*)d_in[3];  // [B,N]

    int BN = in_sizes[3];
    int B  = out_size;
    int N  = BN / B;

    prep_kernel<<<(2 * BN + 127) / 128, 128>>>(points, fea1, fea2, BN);

    int rowtiles = BN / MT;                       // 64
    main_kernel<<<rowtiles * JCH, 128>>>(N);      // 1024 blocks

    init_kernel<<<1, 32>>>((float*)d_out, B);
    reduce_kernel<<<BN / 32, 128>>>(weights, (float*)d_out, N);
}